// round 1
// baseline (speedup 1.0000x reference)
#include <cuda_runtime.h>
#include <math.h>

// Problem constants
#define T_STEPS 300
#define BATCH   64
#define NH      512
#define D_IN    10
#define D_OUT   2
#define ALPHA_F 0.2f

#define OUTS_SZ (T_STEPS*BATCH*D_OUT)
#define RSZ     (T_STEPS*BATCH*NH)
#define BN      (BATCH*NH)

// Persistent device scratch (allowed: __device__ globals, no allocation)
__device__ float g_X[3][BATCH][NH];        // hidden pre-activations: [m1, pmd, s1]
__device__ float g_Wm1pmd_c[NH*NH];        // W_m1_pmd + W_out @ W_fb  (feedback folded)
__device__ float g_bias_pmd[NH];           // b_m1_pmd+b_s1_pmd+b_fb + b_out@W_fb (t>=2)
__device__ float g_bias_pmd_t1[NH];        // b_m1_pmd+b_s1_pmd+b_fb             (t==1)

// ---------------------------------------------------------------------------
// Prep: fold feedback into m1->pmd weight, fold biases, zero state and t=0
// output slices. Runs once per launch (graph-captured), makes every replay
// deterministic.
// ---------------------------------------------------------------------------
__global__ void prep_kernel(const float* __restrict__ W_m1_pmd,
                            const float* __restrict__ W_out,   // [NH][2]
                            const float* __restrict__ W_fb,    // [2][NH]
                            const float* __restrict__ b_m1_pmd,
                            const float* __restrict__ b_s1_pmd,
                            const float* __restrict__ b_fb,
                            const float* __restrict__ b_out,
                            float* __restrict__ d_out)
{
    int idx = blockIdx.x*blockDim.x + threadIdx.x;
    int nth = gridDim.x*blockDim.x;

    for (int i = idx; i < NH*NH; i += nth) {
        int k = i >> 9;
        int j = i & (NH-1);
        g_Wm1pmd_c[i] = W_m1_pmd[i]
                      + W_out[k*2+0]*W_fb[j]
                      + W_out[k*2+1]*W_fb[NH+j];
    }
    for (int j = idx; j < NH; j += nth) {
        float base = b_m1_pmd[j] + b_s1_pmd[j] + b_fb[j];
        g_bias_pmd_t1[j] = base;
        g_bias_pmd[j]    = base + b_out[0]*W_fb[j] + b_out[1]*W_fb[NH+j];
    }
    float* Xf = &g_X[0][0][0];
    for (int i = idx; i < 3*BN; i += nth) Xf[i] = 0.0f;

    float* r0_m1  = d_out + OUTS_SZ;
    float* r0_pmd = r0_m1 + RSZ;
    float* r0_s1  = r0_pmd + RSZ;
    for (int i = idx; i < BN; i += nth) {
        r0_m1[i]  = 0.0f;
        r0_pmd[i] = 0.0f;
        r0_s1[i]  = 0.0f;
    }
}

// ---------------------------------------------------------------------------
// One RNN timestep. Grid = 192 blocks:
//   blocks [0,64)   : pmd region (3 source matmuls)  -- heaviest, launched first
//   blocks [64,128) : m1 region  (2 source matmuls)
//   blocks [128,192): s1 region  (1 source matmul + DIN=10 input term)
// Block = 256 threads = 2 K-halves x 128; each thread accumulates a 2x2 tile
// (rows 2bb,2bb+1 ; cols j0,j0+1) -> inner loop is 2 LDS.64 + 4 FFMA per k.
// A tiles stored k-major with stride 66 (float2-aligned, conflict-free reads).
// Double-buffered LDG->STS prefetch hides L2 latency under tile compute.
// ---------------------------------------------------------------------------
__global__ void __launch_bounds__(256) step_kernel(
    int t,
    const float* __restrict__ W_rec_m1,
    const float* __restrict__ W_pmd_m1,
    const float* __restrict__ b_pmd_m1,
    const float* __restrict__ W_rec_pmd,
    const float* __restrict__ W_s1_pmd,
    const float* __restrict__ W_rec_s1,
    const float* __restrict__ W_in_s1,
    const float* __restrict__ b_in_s1,
    const float* __restrict__ stim,
    float* __restrict__ d_out)
{
    __shared__ float As [2][2][32][66];   // [kh][buf][kk][b] k-major, pad 66
    __shared__ float Wsm[2][2][32][8];    // [kh][buf][kk][j]
    __shared__ float stim_s[BATCH*D_IN];  // current stimulus (s1 blocks)
    __shared__ float red[128][4];         // K-half reduction

    float* r_m1  = d_out + OUTS_SZ;
    float* r_pmd = r_m1 + RSZ;
    float* r_s1  = r_pmd + RSZ;
    const float* rp_m1  = r_m1  + (size_t)(t-1)*BN;
    const float* rp_pmd = r_pmd + (size_t)(t-1)*BN;
    const float* rp_s1  = r_s1  + (size_t)(t-1)*BN;

    const int bid = blockIdx.x;
    const int tid = threadIdx.x;
    const int kh  = tid >> 7;      // K-half: k in [kh*256, kh*256+256)
    const int u   = tid & 127;

    const float* Asrc[3];
    const float* Wsrc[3];
    int nsrc, reg, jbase;
    const float* bias;
    float* rout;

    if (bid < 64) {                         // pmd
        reg = 1; nsrc = 3; jbase = bid*8;
        Asrc[0]=rp_pmd; Wsrc[0]=W_rec_pmd;
        Asrc[1]=rp_m1;  Wsrc[1]=g_Wm1pmd_c;   // feedback folded in
        Asrc[2]=rp_s1;  Wsrc[2]=W_s1_pmd;
        bias = (t==1) ? g_bias_pmd_t1 : g_bias_pmd;
        rout = r_pmd + (size_t)t*BN;
    } else if (bid < 128) {                 // m1
        reg = 0; nsrc = 2; jbase = (bid-64)*8;
        Asrc[0]=rp_m1;  Wsrc[0]=W_rec_m1;
        Asrc[1]=rp_pmd; Wsrc[1]=W_pmd_m1;
        Asrc[2]=rp_m1;  Wsrc[2]=W_rec_m1;    // unused
        bias = b_pmd_m1;
        rout = r_m1 + (size_t)t*BN;
    } else {                                // s1
        reg = 2; nsrc = 1; jbase = (bid-128)*8;
        Asrc[0]=rp_s1; Wsrc[0]=W_rec_s1;
        Asrc[1]=rp_s1; Wsrc[1]=W_rec_s1;     // unused
        Asrc[2]=rp_s1; Wsrc[2]=W_rec_s1;     // unused
        bias = b_in_s1;
        rout = r_s1 + (size_t)t*BN;
    }

    // Load-thread mapping
    const int lane8 = u & 7;       // float4 lane within a row (8 x 4 = 32 k)
    const int arow  = u >> 3;      // 0..15 -> row = p*16 + arow
    const int wkk   = u >> 2;      // 0..31
    const int wj    = (u & 3)*2;

    // Compute-thread mapping (2x2 tile)
    const int bb = u >> 2;         // rows 2bb, 2bb+1
    const int jj = u & 3;          // cols jbase+2jj, +1

    float4 a_stage[4];
    float2 w_stage;

    const int nt = nsrc*8;         // 8 k-tiles of 32 per source per half

    auto load_tile = [&](int ti) {
        int s  = ti >> 3;
        int k0 = kh*256 + (ti & 7)*32;
        const float* A = Asrc[s];
        #pragma unroll
        for (int p = 0; p < 4; p++) {
            int b = p*16 + arow;
            a_stage[p] = *reinterpret_cast<const float4*>(&A[b*NH + k0 + lane8*4]);
        }
        w_stage = *reinterpret_cast<const float2*>(&Wsrc[s][(k0 + wkk)*NH + jbase + wj]);
    };
    auto store_tile = [&](int buf) {
        #pragma unroll
        for (int p = 0; p < 4; p++) {
            int b = p*16 + arow;
            As[kh][buf][lane8*4+0][b] = a_stage[p].x;
            As[kh][buf][lane8*4+1][b] = a_stage[p].y;
            As[kh][buf][lane8*4+2][b] = a_stage[p].z;
            As[kh][buf][lane8*4+3][b] = a_stage[p].w;
        }
        *reinterpret_cast<float2*>(&Wsm[kh][buf][wkk][wj]) = w_stage;
    };

    float acc00=0.f, acc01=0.f, acc10=0.f, acc11=0.f;

    // Prologue
    load_tile(0);
    store_tile(0);
    if (reg == 2) {
        for (int i = tid; i < BATCH*D_IN; i += 256)
            stim_s[i] = stim[t*BATCH*D_IN + i];
    }
    __syncthreads();

    for (int ti = 0; ti < nt; ti++) {
        int buf = ti & 1;
        if (ti + 1 < nt) load_tile(ti + 1);       // prefetch next (LDG in flight)
        #pragma unroll
        for (int kk = 0; kk < 32; kk++) {
            float2 a = *reinterpret_cast<const float2*>(&As [kh][buf][kk][2*bb]);
            float2 w = *reinterpret_cast<const float2*>(&Wsm[kh][buf][kk][2*jj]);
            acc00 = fmaf(a.x, w.x, acc00);
            acc01 = fmaf(a.x, w.y, acc01);
            acc10 = fmaf(a.y, w.x, acc10);
            acc11 = fmaf(a.y, w.y, acc11);
        }
        if (ti + 1 < nt) store_tile(buf ^ 1);     // fill other buffer
        __syncthreads();
    }

    // Reduce the two K-halves
    if (kh == 1) {
        red[u][0]=acc00; red[u][1]=acc01; red[u][2]=acc10; red[u][3]=acc11;
    }
    __syncthreads();
    if (kh == 0) {
        acc00 += red[u][0]; acc01 += red[u][1];
        acc10 += red[u][2]; acc11 += red[u][3];

        const int r0 = 2*bb, r1 = 2*bb + 1;
        const int j0 = jbase + 2*jj, j1 = j0 + 1;

        float b0 = bias[j0], b1 = bias[j1];
        float t00 = acc00 + b0, t01 = acc01 + b1;
        float t10 = acc10 + b0, t11 = acc11 + b1;

        if (reg == 2) {   // s1 input term, K = 10
            #pragma unroll
            for (int k = 0; k < D_IN; k++) {
                float w0 = W_in_s1[k*NH + j0];
                float w1 = W_in_s1[k*NH + j1];
                float s0 = stim_s[r0*D_IN + k];
                float s1v = stim_s[r1*D_IN + k];
                t00 = fmaf(s0,  w0, t00);
                t01 = fmaf(s0,  w1, t01);
                t10 = fmaf(s1v, w0, t10);
                t11 = fmaf(s1v, w1, t11);
            }
        }

        float x00 = g_X[reg][r0][j0], x01 = g_X[reg][r0][j1];
        float x10 = g_X[reg][r1][j0], x11 = g_X[reg][r1][j1];
        x00 = (1.0f-ALPHA_F)*x00 + ALPHA_F*t00;
        x01 = (1.0f-ALPHA_F)*x01 + ALPHA_F*t01;
        x10 = (1.0f-ALPHA_F)*x10 + ALPHA_F*t10;
        x11 = (1.0f-ALPHA_F)*x11 + ALPHA_F*t11;
        g_X[reg][r0][j0] = x00;  g_X[reg][r0][j1] = x01;
        g_X[reg][r1][j0] = x10;  g_X[reg][r1][j1] = x11;

        rout[r0*NH + j0] = tanhf(x00);
        rout[r0*NH + j1] = tanhf(x01);
        rout[r1*NH + j0] = tanhf(x10);
        rout[r1*NH + j1] = tanhf(x11);
    }
}

// ---------------------------------------------------------------------------
// Readout over all timesteps: outs[t] = r_m1[t] @ W_out + b_out (t>=1), 0 at t=0.
// One block per t, 128 threads = 64 batch x 2 outputs.
// ---------------------------------------------------------------------------
__global__ void finale_kernel(const float* __restrict__ W_out,
                              const float* __restrict__ b_out,
                              float* __restrict__ d_out)
{
    const int t = blockIdx.x;
    const int u = threadIdx.x;       // 0..127
    const int b = u >> 1, d = u & 1;

    if (t == 0) { d_out[u] = 0.0f; return; }   // out0 = zeros exactly

    const float* rm = d_out + OUTS_SZ + (size_t)t*BN + b*NH;
    float a0=0.f, a1=0.f, a2=0.f, a3=0.f;
    for (int k = 0; k < NH; k += 4) {
        float4 r4 = *reinterpret_cast<const float4*>(&rm[k]);
        a0 = fmaf(r4.x, W_out[(k+0)*2 + d], a0);
        a1 = fmaf(r4.y, W_out[(k+1)*2 + d], a1);
        a2 = fmaf(r4.z, W_out[(k+2)*2 + d], a2);
        a3 = fmaf(r4.w, W_out[(k+3)*2 + d], a3);
    }
    d_out[t*BATCH*D_OUT + b*D_OUT + d] = b_out[d] + (a0 + a1) + (a2 + a3);
}

// ---------------------------------------------------------------------------
// Launch: prep -> 299 step kernels -> readout. All graph-capturable, no
// allocation, no sync, deterministic.
// ---------------------------------------------------------------------------
extern "C" void kernel_launch(void* const* d_in, const int* in_sizes, int n_in,
                              void* d_out, int out_size)
{
    const float* stim      = (const float*)d_in[0];
    const float* W_rec_m1  = (const float*)d_in[1];
    const float* W_rec_pmd = (const float*)d_in[2];
    const float* W_rec_s1  = (const float*)d_in[3];
    const float* W_pmd_m1  = (const float*)d_in[4];
    const float* b_pmd_m1  = (const float*)d_in[5];
    const float* W_m1_pmd  = (const float*)d_in[6];
    const float* b_m1_pmd  = (const float*)d_in[7];
    const float* W_s1_pmd  = (const float*)d_in[8];
    const float* b_s1_pmd  = (const float*)d_in[9];
    const float* W_in_s1   = (const float*)d_in[10];
    const float* b_in_s1   = (const float*)d_in[11];
    const float* W_out_m1  = (const float*)d_in[12];
    const float* b_out_m1  = (const float*)d_in[13];
    const float* W_fb_pmd  = (const float*)d_in[14];
    const float* b_fb_pmd  = (const float*)d_in[15];
    float* out = (float*)d_out;

    prep_kernel<<<256, 256>>>(W_m1_pmd, W_out_m1, W_fb_pmd,
                              b_m1_pmd, b_s1_pmd, b_fb_pmd, b_out_m1, out);

    for (int t = 1; t < T_STEPS; t++) {
        step_kernel<<<192, 256>>>(t,
            W_rec_m1, W_pmd_m1, b_pmd_m1,
            W_rec_pmd, W_s1_pmd,
            W_rec_s1, W_in_s1, b_in_s1,
            stim, out);
    }

    finale_kernel<<<T_STEPS, 128>>>(W_out_m1, b_out_m1, out);
}